// round 7
// baseline (speedup 1.0000x reference)
#include <cuda_runtime.h>
#include <math.h>

#define Bq 2
#define NQ 1600
#define D 256
#define NH 8
#define HD 32
#define NL 4
#define NP 4
#define DFFN 1024
#define S_TOT 5440
#define NLAYERS 6
#define M_Q (Bq*NQ)      /* 3200 */
#define M_S (Bq*S_TOT)   /* 10880 */

#define BM 128
#define BN 64
#define BK 16

// ---------------- scratch (device globals; no allocations allowed) ----------
__device__ float g_x[M_Q*D];
__device__ float g_pq[M_Q*D];
__device__ float g_pk[M_Q*D];
__device__ float g_pv[M_Q*D];
__device__ float g_ao[M_Q*D];
__device__ float g_t2[M_Q*D];
__device__ float g_off[M_Q*D];
__device__ float g_aw[M_Q*NH*NL*NP];
__device__ float g_val[M_S*D];
__device__ float g_ffn[M_Q*DFFN];

// ---------------- SGEMM v3: C[M,N] = (A+A2)[M,K] @ W[N,K]^T + bias ----------
// 128x64 tile, BK=16, 256 threads, 8x4 per thread, double-buffered smem.
// A2 (optional, may be null) is elementwise-added to A during load.
__device__ __forceinline__ void gemm_tile(const float* __restrict__ A, const float* __restrict__ A2,
                                          const float* __restrict__ W,
                                          const float* __restrict__ bias, float* __restrict__ C,
                                          int M, int N, int K, int relu) {
    __shared__ __align__(16) float As[2][BK][BM+4];
    __shared__ __align__(16) float Ws[2][BK][BN+4];
    int bm = blockIdx.y * BM, bn = blockIdx.x * BN;
    int tid = threadIdx.x;
    int tx = tid & 15;        // N dir: 4 cols each
    int ty = tid >> 4;        // M dir: 8 rows each
    int am = tid >> 1;        // 0..127 (A row within tile)
    int ak = (tid & 1) * 4;   // 0 or 4 (plus +8 second fetch)
    int wn = tid >> 2;        // 0..63  (W row within tile)
    int wk = (tid & 3) * 4;   // 0,4,8,12

    const float* Arow  = A + (size_t)(bm + am) * K;
    const float* A2row = A2 ? A2 + (size_t)(bm + am) * K : 0;
    const float* Wrow  = W + (size_t)(bn + wn) * K;

    float acc[8][4] = {};
    float4 pa0, pa1, pw;

    auto loadg = [&](int k0) {
        pa0 = *(const float4*)(Arow + k0 + ak);
        pa1 = *(const float4*)(Arow + k0 + ak + 8);
        if (A2row) {
            float4 q0 = *(const float4*)(A2row + k0 + ak);
            float4 q1 = *(const float4*)(A2row + k0 + ak + 8);
            pa0.x += q0.x; pa0.y += q0.y; pa0.z += q0.z; pa0.w += q0.w;
            pa1.x += q1.x; pa1.y += q1.y; pa1.z += q1.z; pa1.w += q1.w;
        }
        pw = *(const float4*)(Wrow + k0 + wk);
    };
    auto stos = [&](int s) {
        As[s][ak+0][am] = pa0.x; As[s][ak+1][am] = pa0.y;
        As[s][ak+2][am] = pa0.z; As[s][ak+3][am] = pa0.w;
        As[s][ak+8][am] = pa1.x; As[s][ak+9][am] = pa1.y;
        As[s][ak+10][am] = pa1.z; As[s][ak+11][am] = pa1.w;
        Ws[s][wk+0][wn] = pw.x; Ws[s][wk+1][wn] = pw.y;
        Ws[s][wk+2][wn] = pw.z; Ws[s][wk+3][wn] = pw.w;
    };

    loadg(0); stos(0); __syncthreads();
    int T = K / BK;
    for (int t = 0; t < T; t++) {
        int s = t & 1;
        if (t + 1 < T) loadg((t + 1) * BK);
        #pragma unroll
        for (int k = 0; k < BK; k++) {
            float4 b4  = *(const float4*)&Ws[s][k][tx*4];
            float4 a40 = *(const float4*)&As[s][k][ty*8];
            float4 a41 = *(const float4*)&As[s][k][ty*8 + 4];
            float a[8] = {a40.x, a40.y, a40.z, a40.w, a41.x, a41.y, a41.z, a41.w};
            float b[4] = {b4.x, b4.y, b4.z, b4.w};
            #pragma unroll
            for (int i = 0; i < 8; i++)
                #pragma unroll
                for (int j = 0; j < 4; j++) acc[i][j] = fmaf(a[i], b[j], acc[i][j]);
        }
        if (t + 1 < T) { stos(s ^ 1); __syncthreads(); }
    }

    float4 bv = *(const float4*)&bias[bn + tx*4];
    float bb[4] = {bv.x, bv.y, bv.z, bv.w};
    #pragma unroll
    for (int i = 0; i < 8; i++) {
        int row = bm + ty*8 + i;
        float4 o;
        o.x = acc[i][0] + bb[0]; o.y = acc[i][1] + bb[1];
        o.z = acc[i][2] + bb[2]; o.w = acc[i][3] + bb[3];
        if (relu) {
            o.x = fmaxf(o.x, 0.f); o.y = fmaxf(o.y, 0.f);
            o.z = fmaxf(o.z, 0.f); o.w = fmaxf(o.w, 0.f);
        }
        *(float4*)&C[(size_t)row * N + bn + tx*4] = o;
    }
}

__global__ void __launch_bounds__(256) gemm_v3_kernel(const float* __restrict__ A, const float* __restrict__ A2,
                               const float* __restrict__ W,
                               const float* __restrict__ bias, float* __restrict__ C,
                               int M, int N, int K, int relu) {
    gemm_tile(A, A2, W, bias, C, M, N, K, relu);
}

struct Gemm3 {
    const float* A[3];
    const float* A2[3];
    const float* W[3];
    const float* bias[3];
    float* C[3];
};

__global__ void __launch_bounds__(256) gemm3_kernel(Gemm3 g, int M, int N, int K) {
    int z = blockIdx.z;
    gemm_tile(g.A[z], g.A2[z], g.W[z], g.bias[z], g.C[z], M, N, K, 0);
}

// ---------------- fused flash attention (QK^T -> online softmax -> PV) ------
// blockIdx.x: 64-row Q tile (25), blockIdx.y: b*NH+h (16). 256 threads.
__global__ void __launch_bounds__(256, 2) flash_attn_kernel(const float* __restrict__ q,
        const float* __restrict__ k, const float* __restrict__ v, float* __restrict__ out) {
    __shared__ __align__(16) float Qs[32][68];   // [d][i]
    __shared__ __align__(16) float Ks[32][68];   // [d][j]
    __shared__ __align__(16) float Ps[64][68];   // [i][j]
    __shared__ __align__(16) float Vs[64][36];   // [j][c]
    int bh = blockIdx.y; int b = bh >> 3, h = bh & 7;
    int i0 = blockIdx.x * 64;
    int tid = threadIdx.x, tx = tid & 15, ty = tid >> 4;
    int lr = tid >> 2, l4 = tid & 3;
    const float* qb = q + (size_t)b * NQ * D + h * HD;
    const float* kb = k + (size_t)b * NQ * D + h * HD;
    const float* vb = v + (size_t)b * NQ * D + h * HD;
    const float scale = 0.17677669529663687f;   // 1/sqrt(32)

    // load Q tile (pre-scaled), transposed [d][i]
    #pragma unroll
    for (int rep = 0; rep < 2; rep++) {
        int kk = (l4 + rep * 4) * 4;
        float4 qv = *(const float4*)(qb + (size_t)(i0 + lr) * D + kk);
        Qs[kk+0][lr] = qv.x * scale; Qs[kk+1][lr] = qv.y * scale;
        Qs[kk+2][lr] = qv.z * scale; Qs[kk+3][lr] = qv.w * scale;
    }

    float m_i[4], l_i[4], O[4][2];
    #pragma unroll
    for (int i = 0; i < 4; i++) { m_i[i] = -1e30f; l_i[i] = 0.f; O[i][0] = 0.f; O[i][1] = 0.f; }
    int c0 = tx * 2;

    for (int j0 = 0; j0 < NQ; j0 += 64) {
        #pragma unroll
        for (int rep = 0; rep < 2; rep++) {
            int kk = (l4 + rep * 4) * 4;
            float4 kv = *(const float4*)(kb + (size_t)(j0 + lr) * D + kk);
            Ks[kk+0][lr] = kv.x; Ks[kk+1][lr] = kv.y; Ks[kk+2][lr] = kv.z; Ks[kk+3][lr] = kv.w;
            float4 vv = *(const float4*)(vb + (size_t)(j0 + lr) * D + kk);
            *(float4*)&Vs[lr][kk] = vv;
        }
        __syncthreads();

        float c[4][4] = {};
        #pragma unroll
        for (int kd = 0; kd < 32; kd++) {
            float4 a4 = *(const float4*)&Qs[kd][ty*4];
            float4 b4 = *(const float4*)&Ks[kd][tx*4];
            float a[4] = {a4.x, a4.y, a4.z, a4.w};
            float bb[4] = {b4.x, b4.y, b4.z, b4.w};
            #pragma unroll
            for (int i = 0; i < 4; i++)
                #pragma unroll
                for (int j = 0; j < 4; j++) c[i][j] = fmaf(a[i], bb[j], c[i][j]);
        }

        #pragma unroll
        for (int i = 0; i < 4; i++) {
            float mx = fmaxf(fmaxf(c[i][0], c[i][1]), fmaxf(c[i][2], c[i][3]));
            #pragma unroll
            for (int o = 8; o > 0; o >>= 1) mx = fmaxf(mx, __shfl_xor_sync(0xffffffffu, mx, o));
            float newm = fmaxf(m_i[i], mx);
            float alpha = __expf(m_i[i] - newm);
            m_i[i] = newm;
            float4 e;
            e.x = __expf(c[i][0] - newm); e.y = __expf(c[i][1] - newm);
            e.z = __expf(c[i][2] - newm); e.w = __expf(c[i][3] - newm);
            *(float4*)&Ps[ty*4 + i][tx*4] = e;
            float rs = e.x + e.y + e.z + e.w;
            #pragma unroll
            for (int o = 8; o > 0; o >>= 1) rs += __shfl_xor_sync(0xffffffffu, rs, o);
            l_i[i] = l_i[i] * alpha + rs;
            O[i][0] *= alpha; O[i][1] *= alpha;
        }
        __syncthreads();

        #pragma unroll
        for (int j = 0; j < 64; j += 4) {
            float4 p[4]; float2 vv2[4];
            #pragma unroll
            for (int i = 0; i < 4; i++) p[i] = *(const float4*)&Ps[ty*4 + i][j];
            #pragma unroll
            for (int jj = 0; jj < 4; jj++) vv2[jj] = *(const float2*)&Vs[j + jj][c0];
            #pragma unroll
            for (int i = 0; i < 4; i++) {
                O[i][0] = fmaf(p[i].x, vv2[0].x, O[i][0]);
                O[i][0] = fmaf(p[i].y, vv2[1].x, O[i][0]);
                O[i][0] = fmaf(p[i].z, vv2[2].x, O[i][0]);
                O[i][0] = fmaf(p[i].w, vv2[3].x, O[i][0]);
                O[i][1] = fmaf(p[i].x, vv2[0].y, O[i][1]);
                O[i][1] = fmaf(p[i].y, vv2[1].y, O[i][1]);
                O[i][1] = fmaf(p[i].z, vv2[2].y, O[i][1]);
                O[i][1] = fmaf(p[i].w, vv2[3].y, O[i][1]);
            }
        }
        __syncthreads();
    }

    #pragma unroll
    for (int i = 0; i < 4; i++) {
        float inv = 1.f / l_i[i];
        int row = i0 + ty*4 + i;
        float* ob = out + ((size_t)b * NQ + row) * D + h * HD;
        float2 o2; o2.x = O[i][0] * inv; o2.y = O[i][1] * inv;
        *(float2*)&ob[c0] = o2;
    }
}

// ---------------- residual + layernorm, warp per row (D=256) ----------------
__global__ void __launch_bounds__(256) ln_residual_kernel(const float* __restrict__ x,
        const float* __restrict__ t, const float* __restrict__ gam, const float* __restrict__ bet,
        float* __restrict__ out) {
    int row = (blockIdx.x << 3) + (threadIdx.x >> 5);
    int lane = threadIdx.x & 31;
    const float4* xr = (const float4*)(x + (size_t)row * D);
    const float4* tr = (const float4*)(t + (size_t)row * D);
    float4 x0 = xr[lane*2],   t0 = tr[lane*2];
    float4 x1 = xr[lane*2+1], t1 = tr[lane*2+1];
    float v[8] = {x0.x+t0.x, x0.y+t0.y, x0.z+t0.z, x0.w+t0.w,
                  x1.x+t1.x, x1.y+t1.y, x1.z+t1.z, x1.w+t1.w};
    float s = 0.f;
    #pragma unroll
    for (int i = 0; i < 8; i++) s += v[i];
    #pragma unroll
    for (int o = 16; o > 0; o >>= 1) s += __shfl_xor_sync(0xffffffffu, s, o);
    float mu = s * (1.f / D);
    float sq = 0.f;
    #pragma unroll
    for (int i = 0; i < 8; i++) { float d = v[i] - mu; sq += d * d; }
    #pragma unroll
    for (int o = 16; o > 0; o >>= 1) sq += __shfl_xor_sync(0xffffffffu, sq, o);
    float inv = rsqrtf(sq * (1.f / D) + 1e-5f);
    float4 g0 = ((const float4*)gam)[lane*2], g1 = ((const float4*)gam)[lane*2+1];
    float4 b0 = ((const float4*)bet)[lane*2], b1 = ((const float4*)bet)[lane*2+1];
    float4 o0, o1;
    o0.x = (v[0]-mu)*inv*g0.x + b0.x; o0.y = (v[1]-mu)*inv*g0.y + b0.y;
    o0.z = (v[2]-mu)*inv*g0.z + b0.z; o0.w = (v[3]-mu)*inv*g0.w + b0.w;
    o1.x = (v[4]-mu)*inv*g1.x + b1.x; o1.y = (v[5]-mu)*inv*g1.y + b1.y;
    o1.z = (v[6]-mu)*inv*g1.z + b1.z; o1.w = (v[7]-mu)*inv*g1.w + b1.w;
    float4* orow = (float4*)(out + (size_t)row * D);
    orow[lane*2] = o0; orow[lane*2+1] = o1;
}

// ---------------- multi-scale deformable sampling ----------------
__global__ void ms_deform_kernel(const float* __restrict__ off, const float* __restrict__ aw_raw,
                                 const float* __restrict__ value, const float* __restrict__ refp,
                                 float* __restrict__ out) {
    const int lvl_start[4] = {0, 4096, 5120, 5376};
    const int lvl_w[4] = {64, 32, 16, 8};
    int row = blockIdx.x;
    int b = row / NQ; int q = row % NQ;
    int tid = threadIdx.x;
    int h = tid >> 5, lane = tid & 31;
    const float* awr = aw_raw + (size_t)row * (NH * 16) + h * 16;
    float a = (lane < 16) ? awr[lane] : -1e30f;
    float m = a;
    #pragma unroll
    for (int o = 16; o > 0; o >>= 1) m = fmaxf(m, __shfl_xor_sync(0xffffffffu, m, o));
    float e = (lane < 16) ? __expf(a - m) : 0.f;
    float ssum = e;
    #pragma unroll
    for (int o = 16; o > 0; o >>= 1) ssum += __shfl_xor_sync(0xffffffffu, ssum, o);
    float awn = e / ssum;
    const float* offr = off + (size_t)row * D + h * (NL * NP * 2);
    float acc = 0.f;
    #pragma unroll
    for (int l = 0; l < NL; l++) {
        int Wl = lvl_w[l]; int Hl = Wl;
        float rx = refp[(((size_t)b * NQ + q) * NL + l) * 2 + 0];
        float ry = refp[(((size_t)b * NQ + q) * NL + l) * 2 + 1];
        const float* vbase = value + ((size_t)b * S_TOT + lvl_start[l]) * D + h * HD + lane;
        #pragma unroll
        for (int p = 0; p < NP; p++) {
            float ox = offr[(l * NP + p) * 2 + 0];
            float oy = offr[(l * NP + p) * 2 + 1];
            float xx = (rx + ox / (float)Wl) * (float)Wl - 0.5f;
            float yy = (ry + oy / (float)Hl) * (float)Hl - 0.5f;
            float x0f = floorf(xx), y0f = floorf(yy);
            int x0 = (int)x0f, y0 = (int)y0f;
            float wx1 = xx - x0f, wy1 = yy - y0f;
            float pv = 0.f;
            #pragma unroll
            for (int dy = 0; dy < 2; dy++) {
                #pragma unroll
                for (int dx = 0; dx < 2; dx++) {
                    int xi = x0 + dx, yi = y0 + dy;
                    float w = (dx ? wx1 : 1.f - wx1) * (dy ? wy1 : 1.f - wy1);
                    if (xi >= 0 && xi < Wl && yi >= 0 && yi < Hl)
                        pv = fmaf(w, vbase[(size_t)(yi * Wl + xi) * D], pv);
                }
            }
            float awv = __shfl_sync(0xffffffffu, awn, l * NP + p);
            acc = fmaf(pv, awv, acc);
        }
    }
    out[(size_t)row * D + h * HD + lane] = acc;
}

// ---------------- host orchestration ----------------
static inline void gemm(const float* A, const float* A2, const float* W, const float* bias,
                        float* C, int M, int N, int K, int relu) {
    dim3 grid(N / BN, M / BM);
    gemm_v3_kernel<<<grid, 256>>>(A, A2, W, bias, C, M, N, K, relu);
}

extern "C" void kernel_launch(void* const* d_in, const int* in_sizes, int n_in,
                              void* d_out, int out_size) {
    const float* tgt   = (const float*)d_in[0];
    const float* qpos  = (const float*)d_in[1];
    const float* refp  = (const float*)d_in[2];
    const float* src   = (const float*)d_in[3];
    const float* sa_w_q = (const float*)d_in[4];
    const float* sa_b_q = (const float*)d_in[5];
    const float* sa_w_k = (const float*)d_in[6];
    const float* sa_b_k = (const float*)d_in[7];
    const float* sa_w_v = (const float*)d_in[8];
    const float* sa_b_v = (const float*)d_in[9];
    const float* sa_w_o = (const float*)d_in[10];
    const float* sa_b_o = (const float*)d_in[11];
    const float* ln2_g  = (const float*)d_in[12];
    const float* ln2_b  = (const float*)d_in[13];
    const float* ca_w_off  = (const float*)d_in[14];
    const float* ca_b_off  = (const float*)d_in[15];
    const float* ca_w_attn = (const float*)d_in[16];
    const float* ca_b_attn = (const float*)d_in[17];
    const float* ca_w_val  = (const float*)d_in[18];
    const float* ca_b_val  = (const float*)d_in[19];
    const float* ca_w_out  = (const float*)d_in[20];
    const float* ca_b_out  = (const float*)d_in[21];
    const float* ln1_g  = (const float*)d_in[22];
    const float* ln1_b  = (const float*)d_in[23];
    const float* ffn_w1 = (const float*)d_in[24];
    const float* ffn_b1 = (const float*)d_in[25];
    const float* ffn_w2 = (const float*)d_in[26];
    const float* ffn_b2 = (const float*)d_in[27];
    const float* ln3_g  = (const float*)d_in[28];
    const float* ln3_b  = (const float*)d_in[29];

    float *p_x, *p_pq, *p_pk, *p_pv, *p_ao, *p_t2, *p_off, *p_aw, *p_val, *p_ffn;
    cudaGetSymbolAddress((void**)&p_x,   g_x);
    cudaGetSymbolAddress((void**)&p_pq,  g_pq);
    cudaGetSymbolAddress((void**)&p_pk,  g_pk);
    cudaGetSymbolAddress((void**)&p_pv,  g_pv);
    cudaGetSymbolAddress((void**)&p_ao,  g_ao);
    cudaGetSymbolAddress((void**)&p_t2,  g_t2);
    cudaGetSymbolAddress((void**)&p_off, g_off);
    cudaGetSymbolAddress((void**)&p_aw,  g_aw);
    cudaGetSymbolAddress((void**)&p_val, g_val);
    cudaGetSymbolAddress((void**)&p_ffn, g_ffn);

    const int n_xd = M_Q * D;
    cudaMemcpyAsync(p_x, tgt, sizeof(float) * n_xd, cudaMemcpyDeviceToDevice);

    for (int i = 0; i < NLAYERS; i++) {
        const float* wq = sa_w_q + (size_t)i * D * D;
        const float* bq = sa_b_q + (size_t)i * D;
        const float* wk = sa_w_k + (size_t)i * D * D;
        const float* bk = sa_b_k + (size_t)i * D;
        const float* wv = sa_w_v + (size_t)i * D * D;
        const float* bv = sa_b_v + (size_t)i * D;
        const float* wo = sa_w_o + (size_t)i * D * D;
        const float* bo = sa_b_o + (size_t)i * D;

        // ---- self attention (q = x + qpos fused into GEMM A-load) ----
        Gemm3 g3;
        g3.A[0] = p_x;  g3.A[1] = p_x;  g3.A[2] = p_x;
        g3.A2[0] = qpos; g3.A2[1] = qpos; g3.A2[2] = 0;
        g3.W[0] = wq;  g3.W[1] = wk;  g3.W[2] = wv;
        g3.bias[0] = bq; g3.bias[1] = bk; g3.bias[2] = bv;
        g3.C[0] = p_pq; g3.C[1] = p_pk; g3.C[2] = p_pv;
        gemm3_kernel<<<dim3(D/BN, M_Q/BM, 3), 256>>>(g3, M_Q, D, D);
        flash_attn_kernel<<<dim3(NQ/64, Bq*NH), 256>>>(p_pq, p_pk, p_pv, p_ao);
        gemm(p_ao, 0, wo, bo, p_t2, M_Q, D, D, 0);
        ln_residual_kernel<<<M_Q/8, 256>>>(p_x, p_t2, ln2_g + (size_t)i*D, ln2_b + (size_t)i*D, p_x);

        // ---- cross (MS deformable) attention ----
        gemm(p_x, qpos, ca_w_off  + (size_t)i*256*D, ca_b_off  + (size_t)i*256, p_off, M_Q, 256, D, 0);
        gemm(p_x, qpos, ca_w_attn + (size_t)i*128*D, ca_b_attn + (size_t)i*128, p_aw,  M_Q, 128, D, 0);
        gemm(src, 0,    ca_w_val  + (size_t)i*D*D,   ca_b_val  + (size_t)i*D,   p_val, M_S, D, D, 0);
        ms_deform_kernel<<<M_Q, 256>>>(p_off, p_aw, p_val, refp, p_ao);
        gemm(p_ao, 0, ca_w_out + (size_t)i*D*D, ca_b_out + (size_t)i*D, p_t2, M_Q, D, D, 0);
        ln_residual_kernel<<<M_Q/8, 256>>>(p_x, p_t2, ln1_g + (size_t)i*D, ln1_b + (size_t)i*D, p_x);

        // ---- FFN ----
        gemm(p_x, 0, ffn_w1 + (size_t)i*DFFN*D, ffn_b1 + (size_t)i*DFFN, p_ffn, M_Q, DFFN, D, 1);
        gemm(p_ffn, 0, ffn_w2 + (size_t)i*D*DFFN, ffn_b2 + (size_t)i*D, p_t2, M_Q, D, DFFN, 0);
        ln_residual_kernel<<<M_Q/8, 256>>>(p_x, p_t2, ln3_g + (size_t)i*D, ln3_b + (size_t)i*D, p_x);
    }

    cudaMemcpyAsync(d_out, p_x, sizeof(float) * n_xd, cudaMemcpyDeviceToDevice);
}